// round 2
// baseline (speedup 1.0000x reference)
#include <cuda_runtime.h>
#include <cstdint>

#define BATCH 16
#define NPTS  16384
#define CH    128
#define KNB   9
#define KKC   (KNB*CH)      // 1152
#define TM    32
#define THREADS 256

// Scratch: transposed weights (allowed: __device__ globals, no allocation)
__device__ __align__(16) float g_Wt[KKC*CH];    // [kk][o]  (W_conv transposed)
__device__ __align__(16) float g_Wst[CH*CH];    // [c][o]   (W_skip transposed)

__global__ void prep_kernel(const float* __restrict__ Wc, const float* __restrict__ Ws)
{
    int t = blockIdx.x * blockDim.x + threadIdx.x;
    if (t < KKC*CH) { int o = t / KKC; int kk = t - o*KKC; g_Wt[kk*CH + o] = Wc[t]; }
    if (t < CH*CH)  { int o = t / CH;  int c  = t - o*CH;  g_Wst[c*CH + o] = Ws[t]; }
}

__device__ __forceinline__ unsigned long long ffma2(unsigned long long a,
                                                    unsigned long long b,
                                                    unsigned long long c)
{
    unsigned long long d;
    asm("fma.rn.f32x2 %0, %1, %2, %3;" : "=l"(d) : "l"(a), "l"(b), "l"(c));
    return d;
}
__device__ __forceinline__ unsigned long long pack2(float lo, float hi)
{
    unsigned long long r;
    asm("mov.b64 %0, {%1, %2};" : "=l"(r) : "f"(lo), "f"(hi));
    return r;
}
__device__ __forceinline__ float2 unpack2(unsigned long long v)
{
    float lo, hi;
    asm("mov.b64 {%0, %1}, %2;" : "=f"(lo), "=f"(hi) : "l"(v));
    return make_float2(lo, hi);
}
__device__ __forceinline__ float elu1(float v)
{
    return v > 0.0f ? v : expm1f(v);
}

// Dynamic smem layout (floats): As[32][1152] | Xs[32][128] | Ps[32][81]
#define SMEM_FLOATS (TM*KKC + TM*CH + TM*KNB*KNB)
#define SMEM_BYTES  (SMEM_FLOATS * 4)

__global__ __launch_bounds__(THREADS, 1)
void paiconv_kernel(const float* __restrict__ x,
                    const int*   __restrict__ indices,
                    const float* __restrict__ P,
                    const float* __restrict__ b_conv,
                    const float* __restrict__ b_skip,
                    float*       __restrict__ out)
{
    extern __shared__ float sm[];
    float* As = sm;                  // TM x 1152 (neighbors -> in-place perm+elu)
    float* Xs = As + TM*KKC;         // TM x 128  (self rows, for skip)
    float* Ps = Xs + TM*CH;          // TM x 81

    const int tid = threadIdx.x;
    const int g0  = blockIdx.x * TM;         // first global row (b*N + n)
    const int bb  = g0 >> 14;                // N = 2^14
    const int n0  = g0 & (NPTS - 1);

    // ---------------- Phase 1: gather ----------------
    {
        const float* xb = x + (size_t)bb * NPTS * CH;
        // neighbors: 32 rows * 9 nbrs * 32 float4 = 9216 float4, coalesced 512B/warp
        #pragma unroll
        for (int i = 0; i < 36; i++) {
            int e    = tid + THREADS * i;
            int pair = e >> 5;               // row*9 + j  (same across a warp)
            int c4   = e & 31;               // lane -> consecutive float4
            int row  = pair / 9;
            int j    = pair - row * 9;
            int nidx = indices[(n0 + row) * KNB + j];
            float4 v;
            if (nidx < NPTS) v = *(const float4*)(xb + (size_t)nidx * CH + c4 * 4);
            else             v = make_float4(0.f, 0.f, 0.f, 0.f);  // zero padding rows
            *(float4*)(As + row * KKC + j * CH + c4 * 4) = v;
        }
        // self rows for skip: 1024 float4
        #pragma unroll
        for (int i = 0; i < 4; i++) {
            int e   = tid + THREADS * i;
            int row = e >> 5;
            int c4  = e & 31;
            *(float4*)(Xs + row * CH + c4 * 4) =
                *(const float4*)(xb + (size_t)(n0 + row) * CH + c4 * 4);
        }
        // P rows are contiguous in global: copy 32*81 floats
        const float* Pg = P + (size_t)n0 * (KNB * KNB);
        for (int q = tid; q < TM * KNB * KNB; q += THREADS) Ps[q] = Pg[q];
    }
    __syncthreads();

    // ---------------- Phase 2: perm = P @ nbr, then ELU, in place ----------------
    #pragma unroll
    for (int it = 0; it < (TM * CH) / THREADS; it++) {   // 16
        int task = tid + THREADS * it;
        int row  = task >> 7;
        int c    = task & (CH - 1);
        float* arow = As + row * KKC + c;
        float nb[KNB];
        #pragma unroll
        for (int j = 0; j < KNB; j++) nb[j] = arow[j * CH];
        const float* prow = Ps + row * (KNB * KNB);
        float ov[KNB];
        #pragma unroll
        for (int k = 0; k < KNB; k++) {
            float s = 0.0f;
            #pragma unroll
            for (int j = 0; j < KNB; j++) s = fmaf(prow[k * KNB + j], nb[j], s);
            ov[k] = elu1(s);
        }
        #pragma unroll
        for (int k = 0; k < KNB; k++) arow[k * CH] = ov[k];
    }
    __syncthreads();

    // ---------------- Phase 3: GEMM (conv K=1152, then skip K=128) ----------------
    const int ty = tid >> 5;   // warp id 0..7 -> 4 rows each
    const int tx = tid & 31;   // lane -> 4 consecutive cols (2 packed pairs)

    unsigned long long acc[4][2];
    #pragma unroll
    for (int i = 0; i < 4; i++) { acc[i][0] = 0ull; acc[i][1] = 0ull; }

    const float* Ab0 = As + (ty * 4 + 0) * KKC;
    const float* Ab1 = As + (ty * 4 + 1) * KKC;
    const float* Ab2 = As + (ty * 4 + 2) * KKC;
    const float* Ab3 = As + (ty * 4 + 3) * KKC;

    #pragma unroll 2
    for (int kk = 0; kk < KKC; kk += 4) {
        float a4[4][4];
        {
            float4 v;
            v = *(const float4*)(Ab0 + kk); a4[0][0]=v.x; a4[0][1]=v.y; a4[0][2]=v.z; a4[0][3]=v.w;
            v = *(const float4*)(Ab1 + kk); a4[1][0]=v.x; a4[1][1]=v.y; a4[1][2]=v.z; a4[1][3]=v.w;
            v = *(const float4*)(Ab2 + kk); a4[2][0]=v.x; a4[2][1]=v.y; a4[2][2]=v.z; a4[2][3]=v.w;
            v = *(const float4*)(Ab3 + kk); a4[3][0]=v.x; a4[3][1]=v.y; a4[3][2]=v.z; a4[3][3]=v.w;
        }
        #pragma unroll
        for (int t = 0; t < 4; t++) {
            ulonglong2 w = *(const ulonglong2*)(g_Wt + (kk + t) * CH + tx * 4);
            #pragma unroll
            for (int i = 0; i < 4; i++) {
                unsigned long long aa = pack2(a4[i][t], a4[i][t]);
                acc[i][0] = ffma2(aa, w.x, acc[i][0]);
                acc[i][1] = ffma2(aa, w.y, acc[i][1]);
            }
        }
    }

    // skip GEMM: Xs (32x128) @ W_skip^T
    unsigned long long accs[4][2];
    #pragma unroll
    for (int i = 0; i < 4; i++) { accs[i][0] = 0ull; accs[i][1] = 0ull; }

    const float* Xb0 = Xs + (ty * 4 + 0) * CH;
    const float* Xb1 = Xs + (ty * 4 + 1) * CH;
    const float* Xb2 = Xs + (ty * 4 + 2) * CH;
    const float* Xb3 = Xs + (ty * 4 + 3) * CH;

    #pragma unroll 2
    for (int kk = 0; kk < CH; kk += 4) {
        float a4[4][4];
        {
            float4 v;
            v = *(const float4*)(Xb0 + kk); a4[0][0]=v.x; a4[0][1]=v.y; a4[0][2]=v.z; a4[0][3]=v.w;
            v = *(const float4*)(Xb1 + kk); a4[1][0]=v.x; a4[1][1]=v.y; a4[1][2]=v.z; a4[1][3]=v.w;
            v = *(const float4*)(Xb2 + kk); a4[2][0]=v.x; a4[2][1]=v.y; a4[2][2]=v.z; a4[2][3]=v.w;
            v = *(const float4*)(Xb3 + kk); a4[3][0]=v.x; a4[3][1]=v.y; a4[3][2]=v.z; a4[3][3]=v.w;
        }
        #pragma unroll
        for (int t = 0; t < 4; t++) {
            ulonglong2 w = *(const ulonglong2*)(g_Wst + (kk + t) * CH + tx * 4);
            #pragma unroll
            for (int i = 0; i < 4; i++) {
                unsigned long long aa = pack2(a4[i][t], a4[i][t]);
                accs[i][0] = ffma2(aa, w.x, accs[i][0]);
                accs[i][1] = ffma2(aa, w.y, accs[i][1]);
            }
        }
    }

    // ---------------- Epilogue: elu(conv + b_conv) + skip + b_skip ----------------
    float4 bc = *(const float4*)(b_conv + tx * 4);
    float4 bs = *(const float4*)(b_skip + tx * 4);
    #pragma unroll
    for (int i = 0; i < 4; i++) {
        float2 c0 = unpack2(acc[i][0]);
        float2 c1 = unpack2(acc[i][1]);
        float2 s0 = unpack2(accs[i][0]);
        float2 s1 = unpack2(accs[i][1]);
        float4 r;
        r.x = elu1(c0.x + bc.x) + s0.x + bs.x;
        r.y = elu1(c0.y + bc.y) + s0.y + bs.y;
        r.z = elu1(c1.x + bc.z) + s1.x + bs.z;
        r.w = elu1(c1.y + bc.w) + s1.y + bs.w;
        *(float4*)(out + (size_t)(g0 + ty * 4 + i) * CH + tx * 4) = r;
    }
}

extern "C" void kernel_launch(void* const* d_in, const int* in_sizes, int n_in,
                              void* d_out, int out_size)
{
    const float* x   = (const float*)d_in[0];
    const int*   idx = (const int*)  d_in[1];
    const float* P   = (const float*)d_in[2];
    const float* Wc  = (const float*)d_in[3];
    const float* bc  = (const float*)d_in[4];
    const float* Ws  = (const float*)d_in[5];
    const float* bs  = (const float*)d_in[6];
    float* out = (float*)d_out;

    cudaFuncSetAttribute(paiconv_kernel,
                         cudaFuncAttributeMaxDynamicSharedMemorySize, SMEM_BYTES);

    prep_kernel<<<(KKC*CH + 255) / 256, 256>>>(Wc, Ws);

    int grid = (BATCH * NPTS) / TM;   // 8192
    paiconv_kernel<<<grid, THREADS, SMEM_BYTES>>>(x, idx, P, bc, bs, out);
}

// round 5
// speedup vs baseline: 1.0013x; 1.0013x over previous
#include <cuda_runtime.h>
#include <cstdint>

#define BATCH 16
#define NPTS  16384
#define CH    128
#define KNB   9
#define KKC   (KNB*CH)      // 1152
#define TM    32
#define THREADS 256

// Scratch: transposed weights (allowed: __device__ globals, no allocation)
__device__ __align__(16) float g_Wt[KKC*CH];    // [kk][o]  (W_conv transposed)
__device__ __align__(16) float g_Wst[CH*CH];    // [c][o]   (W_skip transposed)

__global__ void prep_kernel(const float* __restrict__ Wc, const float* __restrict__ Ws)
{
    int t = blockIdx.x * blockDim.x + threadIdx.x;
    if (t < KKC*CH) { int o = t / KKC; int kk = t - o*KKC; g_Wt[kk*CH + o] = Wc[t]; }
    if (t < CH*CH)  { int o = t / CH;  int c  = t - o*CH;  g_Wst[c*CH + o] = Ws[t]; }
}

__device__ __forceinline__ unsigned long long ffma2(unsigned long long a,
                                                    unsigned long long b,
                                                    unsigned long long c)
{
    unsigned long long d;
    asm("fma.rn.f32x2 %0, %1, %2, %3;" : "=l"(d) : "l"(a), "l"(b), "l"(c));
    return d;
}
__device__ __forceinline__ unsigned long long pack2(float lo, float hi)
{
    unsigned long long r;
    asm("mov.b64 %0, {%1, %2};" : "=l"(r) : "f"(lo), "f"(hi));
    return r;
}
__device__ __forceinline__ float2 unpack2(unsigned long long v)
{
    float lo, hi;
    asm("mov.b64 {%0, %1}, %2;" : "=f"(lo), "=f"(hi) : "l"(v));
    return make_float2(lo, hi);
}
__device__ __forceinline__ float elu1(float v)
{
    return v > 0.0f ? v : expm1f(v);
}

// Dynamic smem layout (floats): As[32][1152] | Xs[32][128] | Ps[32][81]
#define SMEM_FLOATS (TM*KKC + TM*CH + TM*KNB*KNB)
#define SMEM_BYTES  (SMEM_FLOATS * 4)

__global__ __launch_bounds__(THREADS, 1)
void paiconv_kernel(const float* __restrict__ x,
                    const int*   __restrict__ indices,
                    const float* __restrict__ P,
                    const float* __restrict__ b_conv,
                    const float* __restrict__ b_skip,
                    float*       __restrict__ out)
{
    extern __shared__ float sm[];
    float* As = sm;                  // TM x 1152 (neighbors -> in-place perm+elu)
    float* Xs = As + TM*KKC;         // TM x 128  (self rows, for skip)
    float* Ps = Xs + TM*CH;          // TM x 81

    const int tid = threadIdx.x;
    const int g0  = blockIdx.x * TM;         // first global row (b*N + n)
    const int bb  = g0 >> 14;                // N = 2^14
    const int n0  = g0 & (NPTS - 1);

    // ---------------- Phase 1: gather ----------------
    {
        const float* xb = x + (size_t)bb * NPTS * CH;
        // neighbors: 32 rows * 9 nbrs * 32 float4 = 9216 float4, coalesced 512B/warp
        #pragma unroll
        for (int i = 0; i < 36; i++) {
            int e    = tid + THREADS * i;
            int pair = e >> 5;               // row*9 + j  (same across a warp)
            int c4   = e & 31;               // lane -> consecutive float4
            int row  = pair / 9;
            int j    = pair - row * 9;
            int nidx = indices[(n0 + row) * KNB + j];
            float4 v;
            if (nidx < NPTS) v = *(const float4*)(xb + (size_t)nidx * CH + c4 * 4);
            else             v = make_float4(0.f, 0.f, 0.f, 0.f);  // zero padding rows
            *(float4*)(As + row * KKC + j * CH + c4 * 4) = v;
        }
        // self rows for skip: 1024 float4
        #pragma unroll
        for (int i = 0; i < 4; i++) {
            int e   = tid + THREADS * i;
            int row = e >> 5;
            int c4  = e & 31;
            *(float4*)(Xs + row * CH + c4 * 4) =
                *(const float4*)(xb + (size_t)(n0 + row) * CH + c4 * 4);
        }
        // P rows are contiguous in global: copy 32*81 floats
        const float* Pg = P + (size_t)n0 * (KNB * KNB);
        for (int q = tid; q < TM * KNB * KNB; q += THREADS) Ps[q] = Pg[q];
    }
    __syncthreads();

    // ---------------- Phase 2: perm = P @ nbr, then ELU, in place ----------------
    #pragma unroll
    for (int it = 0; it < (TM * CH) / THREADS; it++) {   // 16
        int task = tid + THREADS * it;
        int row  = task >> 7;
        int c    = task & (CH - 1);
        float* arow = As + row * KKC + c;
        float nb[KNB];
        #pragma unroll
        for (int j = 0; j < KNB; j++) nb[j] = arow[j * CH];
        const float* prow = Ps + row * (KNB * KNB);
        float ov[KNB];
        #pragma unroll
        for (int k = 0; k < KNB; k++) {
            float s = 0.0f;
            #pragma unroll
            for (int j = 0; j < KNB; j++) s = fmaf(prow[k * KNB + j], nb[j], s);
            ov[k] = elu1(s);
        }
        #pragma unroll
        for (int k = 0; k < KNB; k++) arow[k * CH] = ov[k];
    }
    __syncthreads();

    // ---------------- Phase 3: GEMM (conv K=1152, then skip K=128) ----------------
    const int ty = tid >> 5;   // warp id 0..7 -> 4 rows each
    const int tx = tid & 31;   // lane -> 4 consecutive cols (2 packed pairs)

    unsigned long long acc[4][2];
    #pragma unroll
    for (int i = 0; i < 4; i++) { acc[i][0] = 0ull; acc[i][1] = 0ull; }

    const float* Ab0 = As + (ty * 4 + 0) * KKC;
    const float* Ab1 = As + (ty * 4 + 1) * KKC;
    const float* Ab2 = As + (ty * 4 + 2) * KKC;
    const float* Ab3 = As + (ty * 4 + 3) * KKC;

    #pragma unroll 2
    for (int kk = 0; kk < KKC; kk += 4) {
        float a4[4][4];
        {
            float4 v;
            v = *(const float4*)(Ab0 + kk); a4[0][0]=v.x; a4[0][1]=v.y; a4[0][2]=v.z; a4[0][3]=v.w;
            v = *(const float4*)(Ab1 + kk); a4[1][0]=v.x; a4[1][1]=v.y; a4[1][2]=v.z; a4[1][3]=v.w;
            v = *(const float4*)(Ab2 + kk); a4[2][0]=v.x; a4[2][1]=v.y; a4[2][2]=v.z; a4[2][3]=v.w;
            v = *(const float4*)(Ab3 + kk); a4[3][0]=v.x; a4[3][1]=v.y; a4[3][2]=v.z; a4[3][3]=v.w;
        }
        #pragma unroll
        for (int t = 0; t < 4; t++) {
            ulonglong2 w = *(const ulonglong2*)(g_Wt + (kk + t) * CH + tx * 4);
            #pragma unroll
            for (int i = 0; i < 4; i++) {
                unsigned long long aa = pack2(a4[i][t], a4[i][t]);
                acc[i][0] = ffma2(aa, w.x, acc[i][0]);
                acc[i][1] = ffma2(aa, w.y, acc[i][1]);
            }
        }
    }

    // skip GEMM: Xs (32x128) @ W_skip^T
    unsigned long long accs[4][2];
    #pragma unroll
    for (int i = 0; i < 4; i++) { accs[i][0] = 0ull; accs[i][1] = 0ull; }

    const float* Xb0 = Xs + (ty * 4 + 0) * CH;
    const float* Xb1 = Xs + (ty * 4 + 1) * CH;
    const float* Xb2 = Xs + (ty * 4 + 2) * CH;
    const float* Xb3 = Xs + (ty * 4 + 3) * CH;

    #pragma unroll 2
    for (int kk = 0; kk < CH; kk += 4) {
        float a4[4][4];
        {
            float4 v;
            v = *(const float4*)(Xb0 + kk); a4[0][0]=v.x; a4[0][1]=v.y; a4[0][2]=v.z; a4[0][3]=v.w;
            v = *(const float4*)(Xb1 + kk); a4[1][0]=v.x; a4[1][1]=v.y; a4[1][2]=v.z; a4[1][3]=v.w;
            v = *(const float4*)(Xb2 + kk); a4[2][0]=v.x; a4[2][1]=v.y; a4[2][2]=v.z; a4[2][3]=v.w;
            v = *(const float4*)(Xb3 + kk); a4[3][0]=v.x; a4[3][1]=v.y; a4[3][2]=v.z; a4[3][3]=v.w;
        }
        #pragma unroll
        for (int t = 0; t < 4; t++) {
            ulonglong2 w = *(const ulonglong2*)(g_Wst + (kk + t) * CH + tx * 4);
            #pragma unroll
            for (int i = 0; i < 4; i++) {
                unsigned long long aa = pack2(a4[i][t], a4[i][t]);
                accs[i][0] = ffma2(aa, w.x, accs[i][0]);
                accs[i][1] = ffma2(aa, w.y, accs[i][1]);
            }
        }
    }

    // ---------------- Epilogue: elu(conv + b_conv) + skip + b_skip ----------------
    float4 bc = *(const float4*)(b_conv + tx * 4);
    float4 bs = *(const float4*)(b_skip + tx * 4);
    #pragma unroll
    for (int i = 0; i < 4; i++) {
        float2 c0 = unpack2(acc[i][0]);
        float2 c1 = unpack2(acc[i][1]);
        float2 s0 = unpack2(accs[i][0]);
        float2 s1 = unpack2(accs[i][1]);
        float4 r;
        r.x = elu1(c0.x + bc.x) + s0.x + bs.x;
        r.y = elu1(c0.y + bc.y) + s0.y + bs.y;
        r.z = elu1(c1.x + bc.z) + s1.x + bs.z;
        r.w = elu1(c1.y + bc.w) + s1.y + bs.w;
        *(float4*)(out + (size_t)(g0 + ty * 4 + i) * CH + tx * 4) = r;
    }
}

extern "C" void kernel_launch(void* const* d_in, const int* in_sizes, int n_in,
                              void* d_out, int out_size)
{
    const float* x   = (const float*)d_in[0];
    const int*   idx = (const int*)  d_in[1];
    const float* P   = (const float*)d_in[2];
    const float* Wc  = (const float*)d_in[3];
    const float* bc  = (const float*)d_in[4];
    const float* Ws  = (const float*)d_in[5];
    const float* bs  = (const float*)d_in[6];
    float* out = (float*)d_out;

    cudaFuncSetAttribute(paiconv_kernel,
                         cudaFuncAttributeMaxDynamicSharedMemorySize, SMEM_BYTES);

    prep_kernel<<<(KKC*CH + 255) / 256, 256>>>(Wc, Ws);

    int grid = (BATCH * NPTS) / TM;   // 8192
    paiconv_kernel<<<grid, THREADS, SMEM_BYTES>>>(x, idx, P, bc, bs, out);
}

// round 12
// speedup vs baseline: 3.3302x; 3.3257x over previous
#include <cuda_runtime.h>
#include <cuda_bf16.h>
#include <cstdint>
#include <cstddef>

#define BATCH 16
#define NPTS  16384
#define CH    128
#define KNB   9
#define KKC   (KNB*CH)            // 1152
#define ROWS  (BATCH*NPTS)        // 262144

// ----------------------------------------------------------------------------
// Scratch planes (static __device__ globals — no runtime allocation)
// Weight planes kept in ORIGINAL [o][k] layout (n-major for the MMA B operand).
// ----------------------------------------------------------------------------
__device__ __align__(1024) __nv_bfloat16 g_fhi[(size_t)ROWS * KKC];
__device__ __align__(1024) __nv_bfloat16 g_flo[(size_t)ROWS * KKC];
__device__ __align__(1024) __nv_bfloat16 g_xhi[(size_t)ROWS * CH];
__device__ __align__(1024) __nv_bfloat16 g_xlo[(size_t)ROWS * CH];
__device__ __align__(1024) __nv_bfloat16 g_Whi[CH * KKC];
__device__ __align__(1024) __nv_bfloat16 g_Wlo[CH * KKC];
__device__ __align__(1024) __nv_bfloat16 g_Wshi[CH * CH];
__device__ __align__(1024) __nv_bfloat16 g_Wslo[CH * CH];

// ----------------------------------------------------------------------------
// Helpers
// ----------------------------------------------------------------------------
__device__ __forceinline__ float elu1(float v) { return v > 0.0f ? v : expm1f(v); }

__device__ __forceinline__ void bsplit(float v, __nv_bfloat16& h, __nv_bfloat16& l)
{
    h = __float2bfloat16_rn(v);
    l = __float2bfloat16_rn(v - __bfloat162float(h));
}

__device__ __forceinline__ uint32_t smem_u32(const void* p)
{
    uint32_t a;
    asm("{ .reg .u64 t; cvta.to.shared.u64 t, %1; cvt.u32.u64 %0, t; }" : "=r"(a) : "l"(p));
    return a;
}

#define SWZ(o) ((o) ^ (((o) >> 3) & 0x70))

__device__ __forceinline__ void cp16(uint32_t dst, const void* src)
{
    asm volatile("cp.async.cg.shared.global [%0], [%1], 16;"
                 :: "r"(dst), "l"(src) : "memory");
}
#define CP_COMMIT() asm volatile("cp.async.commit_group;" ::: "memory")
#define CP_WAIT1()  asm volatile("cp.async.wait_group 1;"  ::: "memory")

__device__ __forceinline__ void ldsm4(uint32_t* r, uint32_t addr)
{
    asm volatile("ldmatrix.sync.aligned.m8n8.x4.shared.b16 {%0,%1,%2,%3}, [%4];"
                 : "=r"(r[0]), "=r"(r[1]), "=r"(r[2]), "=r"(r[3]) : "r"(addr));
}

__device__ __forceinline__ void mma16816(float* c, const uint32_t* a, const uint32_t* b)
{
    asm volatile(
        "mma.sync.aligned.m16n8k16.row.col.f32.bf16.bf16.f32 "
        "{%0,%1,%2,%3}, {%4,%5,%6,%7}, {%8,%9}, {%0,%1,%2,%3};"
        : "+f"(c[0]), "+f"(c[1]), "+f"(c[2]), "+f"(c[3])
        : "r"(a[0]), "r"(a[1]), "r"(a[2]), "r"(a[3]), "r"(b[0]), "r"(b[1]));
}

// ----------------------------------------------------------------------------
// Kernel 0: weight plane split (layouts unchanged: [o][k])
// ----------------------------------------------------------------------------
__global__ void prep2_kernel(const float* __restrict__ Wc, const float* __restrict__ Ws)
{
    int t = blockIdx.x * blockDim.x + threadIdx.x;
    if (t < CH * KKC) {
        __nv_bfloat16 h, l; bsplit(Wc[t], h, l);
        g_Whi[t] = h; g_Wlo[t] = l;
    }
    if (t < CH * CH) {
        __nv_bfloat16 h, l; bsplit(Ws[t], h, l);
        g_Wshi[t] = h; g_Wslo[t] = l;
    }
}

// ----------------------------------------------------------------------------
// Kernel 1: gather + per-node 9x9 mix + ELU -> bf16 hi/lo activation planes
// ----------------------------------------------------------------------------
__global__ __launch_bounds__(128)
void mix_kernel(const float* __restrict__ x,
                const int*   __restrict__ indices,
                const float* __restrict__ P)
{
    __shared__ float Ps[KNB * KNB];
    __shared__ int   idxs[KNB];

    const int tid = threadIdx.x;
    const int row = blockIdx.x;           // b*16384 + n
    const int n   = row & (NPTS - 1);
    const int b   = row >> 14;

    if (tid < KNB * KNB) Ps[tid] = P[(size_t)n * (KNB * KNB) + tid];
    if (tid < KNB)       idxs[tid] = indices[n * KNB + tid];
    __syncthreads();

    const float* xb = x + ((size_t)b << 14) * CH;
    const int c = tid;

    float nb[KNB];
    #pragma unroll
    for (int j = 0; j < KNB; j++) {
        int ij = idxs[j];
        nb[j] = (ij < NPTS) ? xb[(size_t)ij * CH + c] : 0.0f;   // pad rows are zero
    }

    {
        float v = xb[(size_t)n * CH + c];
        __nv_bfloat16 h, l; bsplit(v, h, l);
        g_xhi[(size_t)row * CH + c] = h;
        g_xlo[(size_t)row * CH + c] = l;
    }

    const size_t ob = (size_t)row * KKC + c;
    #pragma unroll
    for (int k = 0; k < KNB; k++) {
        float s = 0.0f;
        #pragma unroll
        for (int j = 0; j < KNB; j++) s = fmaf(Ps[k * KNB + j], nb[j], s);
        float f = elu1(s);
        __nv_bfloat16 h, l; bsplit(f, h, l);
        g_fhi[ob + k * CH] = h;
        g_flo[ob + k * CH] = l;
    }
}

// ----------------------------------------------------------------------------
// Kernel 2: mma.sync bf16 split-precision GEMM, cp.async 3-stage pipeline.
// CTA tile: M=128 x N=128. K chunks of 64: 18 conv (acc1), 2 skip (acc2).
// Stage layout: Ahi(16K) | Alo(16K) | Bhi(16K) | Blo(16K) = 64KB, SW128 swizzle.
// ----------------------------------------------------------------------------
#define NCHUNK    20
#define NCONV     18
#define TILE_B    16384
#define STAGE_B   65536
#define NSTAGE    3
#define GEMM_SMEM (NSTAGE * STAGE_B)    // 196608

__device__ __forceinline__ void load_stage(int chunk, uint32_t stage, int m0, int tid)
{
    const __nv_bfloat16 *bAh, *bAl, *bBh, *bBl;
    int kc, strA, strB;
    if (chunk < NCONV) {
        kc = chunk * 64;
        bAh = g_fhi; bAl = g_flo; strA = KKC;
        bBh = g_Whi; bBl = g_Wlo; strB = KKC;
    } else {
        kc = (chunk - NCONV) * 64;
        bAh = g_xhi; bAl = g_xlo; strA = CH;
        bBh = g_Wshi; bBl = g_Wslo; strB = CH;
    }
    #pragma unroll
    for (int i = 0; i < 16; i++) {
        int e   = tid + 256 * i;
        int sub = e >> 10;              // 0:Ahi 1:Alo 2:Bhi 3:Blo
        int idx = e & 1023;
        int r   = idx >> 3;
        int cc  = idx & 7;
        uint32_t dst = stage + sub * TILE_B + SWZ(r * 128 + cc * 16);
        const __nv_bfloat16* src;
        if      (sub == 0) src = bAh + (size_t)(m0 + r) * strA + kc + cc * 8;
        else if (sub == 1) src = bAl + (size_t)(m0 + r) * strA + kc + cc * 8;
        else if (sub == 2) src = bBh + (size_t)r * strB + kc + cc * 8;
        else               src = bBl + (size_t)r * strB + kc + cc * 8;
        cp16(dst, src);
    }
}

__device__ __forceinline__ void compute_chunk(
    uint32_t st, int lane, int warp_m, int warp_n, float acc[2][8][4])
{
    const uint32_t sAhi = st;
    const uint32_t sAlo = st + TILE_B;
    const uint32_t sBhi = st + 2 * TILE_B;
    const uint32_t sBlo = st + 3 * TILE_B;

    // per-lane ldmatrix address components (x4: lanes 0-7 -> matrix0 rows, ...)
    const int rA = ((lane >> 3) & 1) * 8 + (lane & 7);  // matrices 0/1 = m, 2/3 = k+8
    const int cA = (lane >> 4);
    const int rB = (lane >> 4) * 8 + (lane & 7);        // matrices 0/1 = n-tile0, 2/3 = n-tile1
    const int cB = (lane >> 3) & 1;

    #pragma unroll
    for (int s = 0; s < 4; s++) {
        uint32_t ahi[2][4], alo[2][4];
        #pragma unroll
        for (int t = 0; t < 2; t++) {
            int r = warp_m * 32 + t * 16 + rA;
            int c = s * 2 + cA;
            uint32_t off = SWZ(r * 128 + c * 16);
            ldsm4(ahi[t], sAhi + off);
            ldsm4(alo[t], sAlo + off);
        }
        uint32_t bhi[4][4], blo[4][4];
        #pragma unroll
        for (int g = 0; g < 4; g++) {
            int r = warp_n * 64 + g * 16 + rB;
            int c = s * 2 + cB;
            uint32_t off = SWZ(r * 128 + c * 16);
            ldsm4(bhi[g], sBhi + off);
            ldsm4(blo[g], sBlo + off);
        }
        #pragma unroll
        for (int t = 0; t < 2; t++)
            #pragma unroll
            for (int g = 0; g < 4; g++) {
                mma16816(acc[t][2*g],   ahi[t], bhi[g]);
                mma16816(acc[t][2*g+1], ahi[t], bhi[g] + 2);
                mma16816(acc[t][2*g],   alo[t], bhi[g]);
                mma16816(acc[t][2*g+1], alo[t], bhi[g] + 2);
                mma16816(acc[t][2*g],   ahi[t], blo[g]);
                mma16816(acc[t][2*g+1], ahi[t], blo[g] + 2);
            }
    }
}

__global__ __launch_bounds__(256, 1)
void gemm_kernel(const float* __restrict__ b_conv,
                 const float* __restrict__ b_skip,
                 float*       __restrict__ out)
{
    extern __shared__ char smem[];
    const uint32_t sb = smem_u32(smem);
    const int tid  = threadIdx.x;
    const int lane = tid & 31;
    const int wid  = tid >> 5;
    const int warp_m = wid & 3;          // 4 x 32 rows
    const int warp_n = wid >> 2;         // 2 x 64 cols
    const int m0 = blockIdx.x * 128;

    float acc [2][8][4] = {};            // conv accumulators
    float accs[2][8][4] = {};            // skip accumulators

    load_stage(0, sb,           m0, tid); CP_COMMIT();
    load_stage(1, sb + STAGE_B, m0, tid); CP_COMMIT();

    for (int c = 0; c < NCHUNK; c++) {
        CP_WAIT1();
        __syncthreads();
        if (c + 2 < NCHUNK)
            load_stage(c + 2, sb + ((c + 2) % NSTAGE) * STAGE_B, m0, tid);
        CP_COMMIT();
        const uint32_t st = sb + (c % NSTAGE) * STAGE_B;
        if (c < NCONV) compute_chunk(st, lane, warp_m, warp_n, acc);
        else           compute_chunk(st, lane, warp_m, warp_n, accs);
    }

    // Epilogue: out = elu(acc1 + b_conv) + acc2 + b_skip
    const int mrow  = m0 + warp_m * 32 + (lane >> 2);
    const int nbase = warp_n * 64 + 2 * (lane & 3);
    #pragma unroll
    for (int t = 0; t < 2; t++) {
        #pragma unroll
        for (int n = 0; n < 8; n++) {
            int nc = nbase + (n >> 1) * 16 + (n & 1) * 8;
            float bc0 = b_conv[nc], bc1 = b_conv[nc + 1];
            float bs0 = b_skip[nc], bs1 = b_skip[nc + 1];
            float2 v0, v1;
            v0.x = elu1(acc[t][n][0] + bc0) + accs[t][n][0] + bs0;
            v0.y = elu1(acc[t][n][1] + bc1) + accs[t][n][1] + bs1;
            v1.x = elu1(acc[t][n][2] + bc0) + accs[t][n][2] + bs0;
            v1.y = elu1(acc[t][n][3] + bc1) + accs[t][n][3] + bs1;
            *(float2*)(out + (size_t)(mrow + t * 16)     * CH + nc) = v0;
            *(float2*)(out + (size_t)(mrow + t * 16 + 8) * CH + nc) = v1;
        }
    }
}

// ----------------------------------------------------------------------------
// Host side
// ----------------------------------------------------------------------------
extern "C" void kernel_launch(void* const* d_in, const int* in_sizes, int n_in,
                              void* d_out, int out_size)
{
    const float* x   = (const float*)d_in[0];
    const int*   idx = (const int*)  d_in[1];
    const float* P   = (const float*)d_in[2];
    const float* Wc  = (const float*)d_in[3];
    const float* bc  = (const float*)d_in[4];
    const float* Ws  = (const float*)d_in[5];
    const float* bs  = (const float*)d_in[6];
    float* out = (float*)d_out;

    cudaFuncSetAttribute(gemm_kernel,
                         cudaFuncAttributeMaxDynamicSharedMemorySize, GEMM_SMEM);

    prep2_kernel<<<(CH * KKC + 255) / 256, 256>>>(Wc, Ws);
    mix_kernel<<<ROWS, 128>>>(x, idx, P);
    gemm_kernel<<<ROWS / 128, 256, GEMM_SMEM>>>(bc, bs, out);
}

// round 14
// speedup vs baseline: 4.3527x; 1.3070x over previous
#include <cuda_runtime.h>
#include <cuda_fp16.h>
#include <cstdint>
#include <cstddef>

#define BATCH 16
#define NPTS  16384
#define CH    128
#define KNB   9
#define KKC   (KNB*CH)            // 1152
#define ROWS  (BATCH*NPTS)        // 262144

// ----------------------------------------------------------------------------
// Scratch planes (static __device__ globals — no runtime allocation)
// fp16 hi/lo activation split; weights single-rounded fp16 ([o][k] layout).
// ----------------------------------------------------------------------------
__device__ __align__(1024) __half g_fhi[(size_t)ROWS * KKC];
__device__ __align__(1024) __half g_flo[(size_t)ROWS * KKC];
__device__ __align__(1024) __half g_xhi[(size_t)ROWS * CH];
__device__ __align__(1024) __half g_xlo[(size_t)ROWS * CH];
__device__ __align__(1024) __half g_Whi[CH * KKC];
__device__ __align__(1024) __half g_Wshi[CH * CH];

// ----------------------------------------------------------------------------
// Helpers
// ----------------------------------------------------------------------------
__device__ __forceinline__ float elu1(float v) { return v > 0.0f ? v : expm1f(v); }

__device__ __forceinline__ void hsplit(float v, float& h, float& l)
{
    __half hh = __float2half_rn(v);
    h = __half2float(hh);
    l = v - h;                       // exactly representable residual -> fp16
}

__device__ __forceinline__ uint32_t pack2h(float a, float b)
{
    __half2 p = __floats2half2_rn(a, b);
    return *(uint32_t*)&p;
}

__device__ __forceinline__ uint32_t smem_u32(const void* p)
{
    uint32_t a;
    asm("{ .reg .u64 t; cvta.to.shared.u64 t, %1; cvt.u32.u64 %0, t; }" : "=r"(a) : "l"(p));
    return a;
}

#define SWZ(o) ((o) ^ (((o) >> 3) & 0x70))

__device__ __forceinline__ void cp16(uint32_t dst, const void* src)
{
    asm volatile("cp.async.cg.shared.global [%0], [%1], 16;"
                 :: "r"(dst), "l"(src) : "memory");
}
#define CP_COMMIT() asm volatile("cp.async.commit_group;" ::: "memory")
#define CP_WAIT2()  asm volatile("cp.async.wait_group 2;"  ::: "memory")

__device__ __forceinline__ void ldsm4(uint32_t* r, uint32_t addr)
{
    asm volatile("ldmatrix.sync.aligned.m8n8.x4.shared.b16 {%0,%1,%2,%3}, [%4];"
                 : "=r"(r[0]), "=r"(r[1]), "=r"(r[2]), "=r"(r[3]) : "r"(addr));
}

__device__ __forceinline__ void mma16816(float* c, const uint32_t* a, const uint32_t* b)
{
    asm volatile(
        "mma.sync.aligned.m16n8k16.row.col.f32.f16.f16.f32 "
        "{%0,%1,%2,%3}, {%4,%5,%6,%7}, {%8,%9}, {%0,%1,%2,%3};"
        : "+f"(c[0]), "+f"(c[1]), "+f"(c[2]), "+f"(c[3])
        : "r"(a[0]), "r"(a[1]), "r"(a[2]), "r"(a[3]), "r"(b[0]), "r"(b[1]));
}

// ----------------------------------------------------------------------------
// Kernel 0: weight conversion to fp16
// ----------------------------------------------------------------------------
__global__ void prep2_kernel(const float* __restrict__ Wc, const float* __restrict__ Ws)
{
    int t = blockIdx.x * blockDim.x + threadIdx.x;
    if (t < CH * KKC) g_Whi[t]  = __float2half_rn(Wc[t]);
    if (t < CH * CH)  g_Wshi[t] = __float2half_rn(Ws[t]);
}

// ----------------------------------------------------------------------------
// Kernel 1: gather + per-node 9x9 mix + ELU -> fp16 hi/lo activation planes
// Block = 4 rows (1 warp per row). Thread owns 4 channels (float4 / uint2 ops).
// ----------------------------------------------------------------------------
__global__ __launch_bounds__(128)
void mix_kernel(const float* __restrict__ x,
                const int*   __restrict__ indices,
                const float* __restrict__ P)
{
    __shared__ float Ps[4][KNB * KNB];
    __shared__ int   idxs[4][KNB];

    const int tid  = threadIdx.x;
    const int wid  = tid >> 5;
    const int lane = tid & 31;
    const int row  = blockIdx.x * 4 + wid;
    const int n    = row & (NPTS - 1);
    const int b    = row >> 14;

    for (int q = lane; q < KNB * KNB; q += 32) Ps[wid][q] = P[(size_t)n * (KNB*KNB) + q];
    if (lane < KNB) idxs[wid][lane] = indices[n * KNB + lane];
    __syncwarp();

    const float* xb = x + ((size_t)b << 14) * CH;
    const int c4 = lane * 4;

    float4 nb[KNB];
    #pragma unroll
    for (int j = 0; j < KNB; j++) {
        int ij = idxs[wid][j];
        nb[j] = *(const float4*)(xb + (size_t)ij * CH + c4);   // indices always < NPTS
    }

    // skip planes
    {
        float4 v = *(const float4*)(xb + (size_t)n * CH + c4);
        float hx, lx, hy, ly, hz, lz, hw, lw;
        hsplit(v.x, hx, lx); hsplit(v.y, hy, ly);
        hsplit(v.z, hz, lz); hsplit(v.w, hw, lw);
        uint2 ph = make_uint2(pack2h(hx, hy), pack2h(hz, hw));
        uint2 pl = make_uint2(pack2h(lx, ly), pack2h(lz, lw));
        *(uint2*)(g_xhi + (size_t)row * CH + c4) = ph;
        *(uint2*)(g_xlo + (size_t)row * CH + c4) = pl;
    }

    const size_t ob = (size_t)row * KKC + c4;
    #pragma unroll
    for (int k = 0; k < KNB; k++) {
        float sx = 0.f, sy = 0.f, sz = 0.f, sw = 0.f;
        #pragma unroll
        for (int j = 0; j < KNB; j++) {
            float p = Ps[wid][k * KNB + j];
            sx = fmaf(p, nb[j].x, sx); sy = fmaf(p, nb[j].y, sy);
            sz = fmaf(p, nb[j].z, sz); sw = fmaf(p, nb[j].w, sw);
        }
        sx = elu1(sx); sy = elu1(sy); sz = elu1(sz); sw = elu1(sw);
        float hx, lx, hy, ly, hz, lz, hw, lw;
        hsplit(sx, hx, lx); hsplit(sy, hy, ly);
        hsplit(sz, hz, lz); hsplit(sw, hw, lw);
        uint2 ph = make_uint2(pack2h(hx, hy), pack2h(hz, hw));
        uint2 pl = make_uint2(pack2h(lx, ly), pack2h(lz, lw));
        *(uint2*)(g_fhi + ob + k * CH) = ph;
        *(uint2*)(g_flo + ob + k * CH) = pl;
    }
}

// ----------------------------------------------------------------------------
// Kernel 2: mma.sync fp16 2-pass GEMM, cp.async 4-stage pipeline.
// CTA tile: M=128 x N=128. K chunks of 64: 18 conv (acc1), 2 skip (acc2).
// Stage: Ahi(16K) | Alo(16K) | Bhi(16K) = 48KB, SW128 swizzle.
// ----------------------------------------------------------------------------
#define NCHUNK    20
#define NCONV     18
#define TILE_B    16384
#define STAGE_B   49152
#define NSTAGE    4
#define GEMM_SMEM (NSTAGE * STAGE_B)    // 196608

__device__ __forceinline__ void load_stage(int chunk, uint32_t stage, int m0, int tid)
{
    const __half *bAh, *bAl, *bBh;
    int kc, strA, strB;
    if (chunk < NCONV) {
        kc = chunk * 64;
        bAh = g_fhi; bAl = g_flo; strA = KKC;
        bBh = g_Whi; strB = KKC;
    } else {
        kc = (chunk - NCONV) * 64;
        bAh = g_xhi; bAl = g_xlo; strA = CH;
        bBh = g_Wshi; strB = CH;
    }
    #pragma unroll
    for (int i = 0; i < 12; i++) {           // 3072 cp16 / 256 threads
        int e   = tid + 256 * i;
        int sub = e >> 10;                   // 0:Ahi 1:Alo 2:Bhi
        int idx = e & 1023;
        int r   = idx >> 3;
        int cc  = idx & 7;
        uint32_t dst = stage + sub * TILE_B + SWZ(r * 128 + cc * 16);
        const __half* src;
        if      (sub == 0) src = bAh + (size_t)(m0 + r) * strA + kc + cc * 8;
        else if (sub == 1) src = bAl + (size_t)(m0 + r) * strA + kc + cc * 8;
        else               src = bBh + (size_t)r * strB + kc + cc * 8;
        cp16(dst, src);
    }
}

__device__ __forceinline__ void compute_chunk(
    uint32_t st, int lane, int warp_m, int warp_n, float acc[2][8][4])
{
    const uint32_t sAhi = st;
    const uint32_t sAlo = st + TILE_B;
    const uint32_t sBhi = st + 2 * TILE_B;

    const int rA = ((lane >> 3) & 1) * 8 + (lane & 7);
    const int cA = (lane >> 4);
    const int rB = (lane >> 4) * 8 + (lane & 7);
    const int cB = (lane >> 3) & 1;

    #pragma unroll
    for (int s = 0; s < 4; s++) {
        uint32_t ahi[2][4], alo[2][4];
        #pragma unroll
        for (int t = 0; t < 2; t++) {
            int r = warp_m * 32 + t * 16 + rA;
            int c = s * 2 + cA;
            uint32_t off = SWZ(r * 128 + c * 16);
            ldsm4(ahi[t], sAhi + off);
            ldsm4(alo[t], sAlo + off);
        }
        uint32_t bhi[4][4];
        #pragma unroll
        for (int g = 0; g < 4; g++) {
            int r = warp_n * 64 + g * 16 + rB;
            int c = s * 2 + cB;
            ldsm4(bhi[g], sBhi + SWZ(r * 128 + c * 16));
        }
        #pragma unroll
        for (int t = 0; t < 2; t++)
            #pragma unroll
            for (int g = 0; g < 4; g++) {
                mma16816(acc[t][2*g],   ahi[t], bhi[g]);
                mma16816(acc[t][2*g+1], ahi[t], bhi[g] + 2);
                mma16816(acc[t][2*g],   alo[t], bhi[g]);
                mma16816(acc[t][2*g+1], alo[t], bhi[g] + 2);
            }
    }
}

__global__ __launch_bounds__(256, 1)
void gemm_kernel(const float* __restrict__ b_conv,
                 const float* __restrict__ b_skip,
                 float*       __restrict__ out)
{
    extern __shared__ char smem[];
    const uint32_t sb = smem_u32(smem);
    const int tid  = threadIdx.x;
    const int lane = tid & 31;
    const int wid  = tid >> 5;
    const int warp_m = wid & 3;          // 4 x 32 rows
    const int warp_n = wid >> 2;         // 2 x 64 cols
    const int m0 = blockIdx.x * 128;

    float acc [2][8][4] = {};            // conv accumulators
    float accs[2][8][4] = {};            // skip accumulators

    load_stage(0, sb,               m0, tid); CP_COMMIT();
    load_stage(1, sb +     STAGE_B, m0, tid); CP_COMMIT();
    load_stage(2, sb + 2 * STAGE_B, m0, tid); CP_COMMIT();

    for (int c = 0; c < NCHUNK; c++) {
        CP_WAIT2();
        __syncthreads();
        if (c + 3 < NCHUNK)
            load_stage(c + 3, sb + ((c + 3) & 3) * STAGE_B, m0, tid);
        CP_COMMIT();
        const uint32_t st = sb + (c & 3) * STAGE_B;
        if (c < NCONV) compute_chunk(st, lane, warp_m, warp_n, acc);
        else           compute_chunk(st, lane, warp_m, warp_n, accs);
    }

    // Epilogue: out = elu(acc1 + b_conv) + acc2 + b_skip
    const int mrow  = m0 + warp_m * 32 + (lane >> 2);
    const int nbase = warp_n * 64 + 2 * (lane & 3);
    #pragma unroll
    for (int t = 0; t < 2; t++) {
        #pragma unroll
        for (int n = 0; n < 8; n++) {
            int nc = nbase + (n >> 1) * 16 + (n & 1) * 8;
            float bc0 = b_conv[nc], bc1 = b_conv[nc + 1];
            float bs0 = b_skip[nc], bs1 = b_skip[nc + 1];
            float2 v0, v1;
            v0.x = elu1(acc[t][n][0] + bc0) + accs[t][n][0] + bs0;
            v0.y = elu1(acc[t][n][1] + bc1) + accs[t][n][1] + bs1;
            v1.x = elu1(acc[t][n][2] + bc0) + accs[t][n][2] + bs0;
            v1.y = elu1(acc[t][n][3] + bc1) + accs[t][n][3] + bs1;
            *(float2*)(out + (size_t)(mrow + t * 16)     * CH + nc) = v0;
            *(float2*)(out + (size_t)(mrow + t * 16 + 8) * CH + nc) = v1;
        }
    }
}

// ----------------------------------------------------------------------------
// Host side
// ----------------------------------------------------------------------------
extern "C" void kernel_launch(void* const* d_in, const int* in_sizes, int n_in,
                              void* d_out, int out_size)
{
    const float* x   = (const float*)d_in[0];
    const int*   idx = (const int*)  d_in[1];
    const float* P   = (const float*)d_in[2];
    const float* Wc  = (const float*)d_in[3];
    const float* bc  = (const float*)d_in[4];
    const float* Ws  = (const float*)d_in[5];
    const float* bs  = (const float*)d_in[6];
    float* out = (float*)d_out;

    cudaFuncSetAttribute(gemm_kernel,
                         cudaFuncAttributeMaxDynamicSharedMemorySize, GEMM_SMEM);

    prep2_kernel<<<(CH * KKC + 255) / 256, 256>>>(Wc, Ws);
    mix_kernel<<<ROWS / 4, 128>>>(x, idx, P);
    gemm_kernel<<<ROWS / 128, 256, GEMM_SMEM>>>(bc, bs, out);
}

// round 17
// speedup vs baseline: 5.4148x; 1.2440x over previous
#include <cuda_runtime.h>
#include <cuda_fp16.h>
#include <cstdint>
#include <cstddef>

#define BATCH 16
#define NPTS  16384
#define CH    128
#define KNB   9
#define KKC   (KNB*CH)            // 1152
#define ROWS  (BATCH*NPTS)        // 262144

// ----------------------------------------------------------------------------
// Scratch planes (static __device__ globals — no runtime allocation)
// Single-rounded fp16 activations and weights ([o][k] layout for W).
// ----------------------------------------------------------------------------
__device__ __align__(1024) __half g_f [(size_t)ROWS * KKC];   // 604 MB
__device__ __align__(1024) __half g_xh[(size_t)ROWS * CH];    // 67 MB
__device__ __align__(1024) __half g_Wh [CH * KKC];
__device__ __align__(1024) __half g_Wsh[CH * CH];

// ----------------------------------------------------------------------------
// Helpers
// ----------------------------------------------------------------------------
__device__ __forceinline__ float elu1(float v) { return v > 0.0f ? v : expm1f(v); }

__device__ __forceinline__ uint32_t pack2h(float a, float b)
{
    __half2 p = __floats2half2_rn(a, b);
    return *(uint32_t*)&p;
}

__device__ __forceinline__ uint32_t smem_u32(const void* p)
{
    uint32_t a;
    asm("{ .reg .u64 t; cvta.to.shared.u64 t, %1; cvt.u32.u64 %0, t; }" : "=r"(a) : "l"(p));
    return a;
}

#define SWZ(o) ((o) ^ (((o) >> 3) & 0x70))

__device__ __forceinline__ void cp16(uint32_t dst, const void* src)
{
    asm volatile("cp.async.cg.shared.global [%0], [%1], 16;"
                 :: "r"(dst), "l"(src) : "memory");
}
#define CP_COMMIT() asm volatile("cp.async.commit_group;" ::: "memory")
#define CP_WAIT3()  asm volatile("cp.async.wait_group 3;"  ::: "memory")

__device__ __forceinline__ void ldsm4(uint32_t* r, uint32_t addr)
{
    asm volatile("ldmatrix.sync.aligned.m8n8.x4.shared.b16 {%0,%1,%2,%3}, [%4];"
                 : "=r"(r[0]), "=r"(r[1]), "=r"(r[2]), "=r"(r[3]) : "r"(addr));
}

__device__ __forceinline__ void mma16816(float* c, const uint32_t* a, const uint32_t* b)
{
    asm volatile(
        "mma.sync.aligned.m16n8k16.row.col.f32.f16.f16.f32 "
        "{%0,%1,%2,%3}, {%4,%5,%6,%7}, {%8,%9}, {%0,%1,%2,%3};"
        : "+f"(c[0]), "+f"(c[1]), "+f"(c[2]), "+f"(c[3])
        : "r"(a[0]), "r"(a[1]), "r"(a[2]), "r"(a[3]), "r"(b[0]), "r"(b[1]));
}

// ----------------------------------------------------------------------------
// Kernel 0: weight conversion to fp16
// ----------------------------------------------------------------------------
__global__ void prep2_kernel(const float* __restrict__ Wc, const float* __restrict__ Ws)
{
    int t = blockIdx.x * blockDim.x + threadIdx.x;
    if (t < CH * KKC) g_Wh[t]  = __float2half_rn(Wc[t]);
    if (t < CH * CH)  g_Wsh[t] = __float2half_rn(Ws[t]);
}

// ----------------------------------------------------------------------------
// Kernel 1: gather + per-node 9x9 mix + ELU -> fp16 activation plane
// Block = 4 rows (1 warp per row). Thread owns 4 channels.
// ----------------------------------------------------------------------------
__global__ __launch_bounds__(128)
void mix_kernel(const float* __restrict__ x,
                const int*   __restrict__ indices,
                const float* __restrict__ P)
{
    __shared__ float Ps[4][KNB * KNB];
    __shared__ int   idxs[4][KNB];

    const int tid  = threadIdx.x;
    const int wid  = tid >> 5;
    const int lane = tid & 31;
    const int row  = blockIdx.x * 4 + wid;
    const int n    = row & (NPTS - 1);
    const int b    = row >> 14;

    for (int q = lane; q < KNB * KNB; q += 32) Ps[wid][q] = P[(size_t)n * (KNB*KNB) + q];
    if (lane < KNB) idxs[wid][lane] = indices[n * KNB + lane];
    __syncwarp();

    const float* xb = x + ((size_t)b << 14) * CH;
    const int c4 = lane * 4;

    float4 nb[KNB];
    #pragma unroll
    for (int j = 0; j < KNB; j++) {
        int ij = idxs[wid][j];
        nb[j] = *(const float4*)(xb + (size_t)ij * CH + c4);   // indices always < NPTS
    }

    // skip plane (fp16 copy of x)
    {
        float4 v = *(const float4*)(xb + (size_t)n * CH + c4);
        *(uint2*)(g_xh + (size_t)row * CH + c4) =
            make_uint2(pack2h(v.x, v.y), pack2h(v.z, v.w));
    }

    const size_t ob = (size_t)row * KKC + c4;
    #pragma unroll
    for (int k = 0; k < KNB; k++) {
        float sx = 0.f, sy = 0.f, sz = 0.f, sw = 0.f;
        #pragma unroll
        for (int j = 0; j < KNB; j++) {
            float p = Ps[wid][k * KNB + j];
            sx = fmaf(p, nb[j].x, sx); sy = fmaf(p, nb[j].y, sy);
            sz = fmaf(p, nb[j].z, sz); sw = fmaf(p, nb[j].w, sw);
        }
        *(uint2*)(g_f + ob + k * CH) =
            make_uint2(pack2h(elu1(sx), elu1(sy)), pack2h(elu1(sz), elu1(sw)));
    }
}

// ----------------------------------------------------------------------------
// Kernel 2: mma.sync fp16 single-pass GEMM, cp.async 5-stage pipeline.
// CTA tile: M=128 x N=128. K chunks of 64: 18 conv (acc1), 2 skip (acc2).
// Stage: A(16K) | B(16K) = 32KB, SW128 swizzle.
// ----------------------------------------------------------------------------
#define NCHUNK    20
#define NCONV     18
#define TILE_B    16384
#define STAGE_B   32768
#define NSTAGE    5
#define GEMM_SMEM (NSTAGE * STAGE_B)    // 163840

__device__ __forceinline__ void load_stage(int chunk, uint32_t stage, int m0, int tid)
{
    const __half *bA, *bB;
    int kc, strA, strB;
    if (chunk < NCONV) {
        kc = chunk * 64;
        bA = g_f;  strA = KKC;
        bB = g_Wh; strB = KKC;
    } else {
        kc = (chunk - NCONV) * 64;
        bA = g_xh;  strA = CH;
        bB = g_Wsh; strB = CH;
    }
    #pragma unroll
    for (int i = 0; i < 8; i++) {            // 2048 cp16 / 256 threads
        int e   = tid + 256 * i;
        int sub = e >> 10;                   // 0:A 1:B
        int idx = e & 1023;
        int r   = idx >> 3;
        int cc  = idx & 7;
        uint32_t dst = stage + sub * TILE_B + SWZ(r * 128 + cc * 16);
        const __half* src = (sub == 0)
            ? bA + (size_t)(m0 + r) * strA + kc + cc * 8
            : bB + (size_t)r * strB + kc + cc * 8;
        cp16(dst, src);
    }
}

__device__ __forceinline__ void compute_chunk(
    uint32_t st, int lane, int warp_m, int warp_n, float acc[2][8][4])
{
    const uint32_t sA = st;
    const uint32_t sB = st + TILE_B;

    const int rA = ((lane >> 3) & 1) * 8 + (lane & 7);
    const int cA = (lane >> 4);
    const int rB = (lane >> 4) * 8 + (lane & 7);
    const int cB = (lane >> 3) & 1;

    #pragma unroll
    for (int s = 0; s < 4; s++) {
        uint32_t a[2][4];
        #pragma unroll
        for (int t = 0; t < 2; t++) {
            int r = warp_m * 32 + t * 16 + rA;
            int c = s * 2 + cA;
            ldsm4(a[t], sA + SWZ(r * 128 + c * 16));
        }
        uint32_t bqq[4][4];
        #pragma unroll
        for (int g = 0; g < 4; g++) {
            int r = warp_n * 64 + g * 16 + rB;
            int c = s * 2 + cB;
            ldsm4(bqq[g], sB + SWZ(r * 128 + c * 16));
        }
        #pragma unroll
        for (int t = 0; t < 2; t++)
            #pragma unroll
            for (int g = 0; g < 4; g++) {
                mma16816(acc[t][2*g],   a[t], bqq[g]);
                mma16816(acc[t][2*g+1], a[t], bqq[g] + 2);
            }
    }
}

__global__ __launch_bounds__(256, 1)
void gemm_kernel(const float* __restrict__ b_conv,
                 const float* __restrict__ b_skip,
                 float*       __restrict__ out)
{
    extern __shared__ char smem[];
    const uint32_t sb = smem_u32(smem);
    const int tid  = threadIdx.x;
    const int lane = tid & 31;
    const int wid  = tid >> 5;
    const int warp_m = wid & 3;          // 4 x 32 rows
    const int warp_n = wid >> 2;         // 2 x 64 cols
    const int m0 = blockIdx.x * 128;

    float acc [2][8][4] = {};            // conv accumulators
    float accs[2][8][4] = {};            // skip accumulators

    load_stage(0, sb,               m0, tid); CP_COMMIT();
    load_stage(1, sb +     STAGE_B, m0, tid); CP_COMMIT();
    load_stage(2, sb + 2 * STAGE_B, m0, tid); CP_COMMIT();
    load_stage(3, sb + 3 * STAGE_B, m0, tid); CP_COMMIT();

    int sc = 0;                          // stage index of chunk c (mod 5)
    for (int c = 0; c < NCHUNK; c++) {
        CP_WAIT3();
        __syncthreads();
        if (c + 4 < NCHUNK) {
            int sl = sc + 4; if (sl >= NSTAGE) sl -= NSTAGE;
            load_stage(c + 4, sb + sl * STAGE_B, m0, tid);
        }
        CP_COMMIT();
        const uint32_t st = sb + sc * STAGE_B;
        if (c < NCONV) compute_chunk(st, lane, warp_m, warp_n, acc);
        else           compute_chunk(st, lane, warp_m, warp_n, accs);
        if (++sc == NSTAGE) sc = 0;
    }

    // Epilogue: out = elu(acc1 + b_conv) + acc2 + b_skip
    const int mrow  = m0 + warp_m * 32 + (lane >> 2);
    const int nbase = warp_n * 64 + 2 * (lane & 3);
    #pragma unroll
    for (int t = 0; t < 2; t++) {
        #pragma unroll
        for (int n = 0; n < 8; n++) {
            int nc = nbase + (n >> 1) * 16 + (n & 1) * 8;
            float bc0 = b_conv[nc], bc1 = b_conv[nc + 1];
            float bs0 = b_skip[nc], bs1 = b_skip[nc + 1];
            float2 v0, v1;
            v0.x = elu1(acc[t][n][0] + bc0) + accs[t][n][0] + bs0;
            v0.y = elu1(acc[t][n][1] + bc1) + accs[t][n][1] + bs1;
            v1.x = elu1(acc[t][n][2] + bc0) + accs[t][n][2] + bs0;
            v1.y = elu1(acc[t][n][3] + bc1) + accs[t][n][3] + bs1;
            *(float2*)(out + (size_t)(mrow + t * 16)     * CH + nc) = v0;
            *(float2*)(out + (size_t)(mrow + t * 16 + 8) * CH + nc) = v1;
        }
    }
}

// ----------------------------------------------------------------------------
// Host side
// ----------------------------------------------------------------------------
extern "C" void kernel_launch(void* const* d_in, const int* in_sizes, int n_in,
                              void* d_out, int out_size)
{
    const float* x   = (const float*)d_in[0];
    const int*   idx = (const int*)  d_in[1];
    const float* P   = (const float*)d_in[2];
    const float* Wc  = (const float*)d_in[3];
    const float* bc  = (const float*)d_in[4];
    const float* Ws  = (const float*)d_in[5];
    const float* bs  = (const float*)d_in[6];
    float* out = (float*)d_out;

    cudaFuncSetAttribute(gemm_kernel,
                         cudaFuncAttributeMaxDynamicSharedMemorySize, GEMM_SMEM);

    prep2_kernel<<<(CH * KKC + 255) / 256, 256>>>(Wc, Ws);
    mix_kernel<<<ROWS / 4, 128>>>(x, idx, P);
    gemm_kernel<<<ROWS / 128, 256, GEMM_SMEM>>>(bc, bs, out);
}